// round 16
// baseline (speedup 1.0000x reference)
#include <cuda_runtime.h>
#include <cuda_fp16.h>
#include <cstdint>

#define Nb  8
#define Ssz 1024
#define Esz 1024
#define Hn  16
#define DKs 64
#define NSE (Nb*Ssz*Esz)                 // 8388608
#define NHSS (134217728)
#define NMW (Nb*Ssz*32)                  // mask words: 262144
#define NROWS (Hn*Nb*Ssz)                // 131072

// fp32 buffers (tf32-rounded values stored as fp32)
__device__ float g_Q[NSE], g_K[NSE];     // rounded Q,K [n,s,h,d]
__device__ float g_Vt[NSE];              // rounded V transposed [nh][d][t]
__device__ float g_O[NSE];               // rounded attention output
__device__ float g_Wt[4*Esz*Esz];        // rounded transposed weights [n][k]
__device__ unsigned g_mbits[NMW];        // mask bitwords [nb][row][col/32]
__device__ float g_rowsum[NROWS];        // per (nh,row) sum of exp
__device__ __half g_Pe[NHSS];            // exp scratch (softmax numerators, fp16)
__device__ float g_attn_fb[NHSS];        // fallback attn output (never in practice)

#define CPA16(saddr, gptr) asm volatile("cp.async.cg.shared.global [%0], [%1], 16;\n" :: "r"(saddr), "l"(gptr))
#define CPCOMMIT() asm volatile("cp.async.commit_group;\n")
#define CPWAIT(n)  asm volatile("cp.async.wait_group %0;\n" :: "n"(n))
#define LDSM4(r0,r1,r2,r3,a) asm volatile( \
  "ldmatrix.sync.aligned.m8n8.x4.shared.b16 {%0,%1,%2,%3}, [%4];" \
  : "=r"(r0),"=r"(r1),"=r"(r2),"=r"(r3) : "r"(a))
#define LDSM2(r0,r1,a) asm volatile( \
  "ldmatrix.sync.aligned.m8n8.x2.shared.b16 {%0,%1}, [%2];" \
  : "=r"(r0),"=r"(r1) : "r"(a))

__device__ __forceinline__ float rtf(float x) {
  unsigned u;
  asm("cvt.rna.tf32.f32 %0, %1;" : "=r"(u) : "f"(x));
  return __uint_as_float(u);
}
__device__ __forceinline__ unsigned rtfu(unsigned x) {
  unsigned u;
  asm("cvt.rna.tf32.f32 %0, %1;" : "=r"(u) : "r"(x));
  return u;
}

__device__ __forceinline__ void mma8(float* c, const unsigned* a, unsigned b0, unsigned b1) {
  asm volatile(
      "mma.sync.aligned.m16n8k8.row.col.f32.tf32.tf32.f32 "
      "{%0,%1,%2,%3}, {%4,%5,%6,%7}, {%8,%9}, {%0,%1,%2,%3};\n"
      : "+f"(c[0]), "+f"(c[1]), "+f"(c[2]), "+f"(c[3])
      : "r"(a[0]), "r"(a[1]), "r"(a[2]), "r"(a[3]), "r"(b0), "r"(b1));
}

// tf32 warp-tile compute over CH k8-chunks. A,B fp32 smem tiles, pitch in words.
// RNDA: apply tf32 rounding to A fragments in registers (for raw fp32 A).
template <int MT, int NT, int PITCH, int CH, bool RNDA = false>
__device__ __forceinline__ void compute_tf(
    const float* A, const float* B, int wm0, int wn0, float (&acc)[MT][NT][4]) {
  const int lane = threadIdx.x & 31;
  unsigned aA = (unsigned)__cvta_generic_to_shared(A);
  unsigned aB = (unsigned)__cvta_generic_to_shared(B);
#pragma unroll
  for (int c = 0; c < CH; c++) {
    unsigned a[MT][4];
#pragma unroll
    for (int mt = 0; mt < MT; mt++) {
      unsigned off = (unsigned)((((wm0 + 16*mt + (lane & 15))*PITCH) + c*8 + (lane >> 4)*4)*4);
      LDSM4(a[mt][0], a[mt][1], a[mt][2], a[mt][3], aA + off);
      if (RNDA) {
        a[mt][0] = rtfu(a[mt][0]); a[mt][1] = rtfu(a[mt][1]);
        a[mt][2] = rtfu(a[mt][2]); a[mt][3] = rtfu(a[mt][3]);
      }
    }
#pragma unroll
    for (int nt = 0; nt < NT; nt++) {
      unsigned off = (unsigned)((((wn0 + 8*nt + (lane & 7))*PITCH) + c*8 + ((lane >> 3) & 1)*4)*4);
      unsigned b0, b1;
      LDSM2(b0, b1, aB + off);
#pragma unroll
      for (int mt = 0; mt < MT; mt++) mma8(acc[mt][nt], a[mt], b0, b1);
    }
  }
}

// All 4 weight transposes in one launch: W[k][n] -> Wt[n][k], rounded. z=which.
__global__ __launch_bounds__(256) void transpose_round4(
    const float* __restrict__ w0, const float* __restrict__ w1,
    const float* __restrict__ w2, const float* __restrict__ w3,
    float* __restrict__ WtBase) {
  const float* W = blockIdx.z == 0 ? w0 : blockIdx.z == 1 ? w1 :
                   blockIdx.z == 2 ? w2 : w3;
  float* Wt = WtBase + (size_t)blockIdx.z*Esz*Esz;
  __shared__ float tile[32][33];
  int bx = blockIdx.x*32, by = blockIdx.y*32;
  int t = threadIdx.x, x = t & 31, y = t >> 5;
#pragma unroll
  for (int i = 0; i < 4; i++)
    tile[y + 8*i][x] = W[(size_t)(by + y + 8*i)*1024 + bx + x];
  __syncthreads();
#pragma unroll
  for (int i = 0; i < 4; i++)
    Wt[(size_t)(bx + y + 8*i)*1024 + by + x] = rtf(tile[x][y + 8*i]);
}

// mask int32 -> 1 bit per entry
__global__ void mask_bits(const int* __restrict__ mask, unsigned* __restrict__ mb) {
  int lane = threadIdx.x & 31;
  int warp = (blockIdx.x*blockDim.x + threadIdx.x) >> 5;
  int nwarps = (gridDim.x*blockDim.x) >> 5;
  for (int w = warp; w < NMW; w += nwarps) {
    int v = mask[(size_t)w*32 + lane];
    unsigned b = __ballot_sync(0xffffffffu, v != 0);
    if (lane == 0) mb[w] = b;
  }
}

// load 128x32 fp32 tile into stage (pitch 36 words)
__device__ __forceinline__ void proj_issue(
    unsigned st, const float* __restrict__ A, const float* __restrict__ B,
    int kt, int tid) {
#pragma unroll
  for (int j = 0; j < 4; j++) {
    int c = tid + 256*j;
    int row = c >> 3, ch = c & 7;
    unsigned d = st + (unsigned)((row*36 + ch*4)*4);
    CPA16(d,          A + (size_t)row*1024 + kt + ch*4);
    CPA16(d + 18432u, B + (size_t)row*1024 + kt + ch*4);
  }
}

// ---------------------------------------------------------------------------
// Projection GEMM core (tf32): 3-stage cp.async ring, ONE sync per k-tile.
// EPI: 0 = rounded fp32 (Q/K), 1 = plain fp32 out, 2 = rounded Vt-transposed.
// RNDA: round A fragments inline (raw fp32 input). dyn smem 110592.
// ---------------------------------------------------------------------------
template <bool RNDA>
__device__ __forceinline__ void proj_core(
    float* sm, const float* Af, const float* Wt, const float* bias,
    float* Cf, int epi, int m0, int n0) {
  const int tid = threadIdx.x, wid = tid >> 5, lane = tid & 31;
  const int gr = lane >> 2, q = lane & 3;
  const int wm0 = (wid >> 2)*64, wn0 = (wid & 3)*32;
  unsigned smu = (unsigned)__cvta_generic_to_shared(sm);
  const float* A = Af + (size_t)m0*1024;
  const float* B = Wt + (size_t)n0*1024;
  float acc[4][4][4] = {};
  proj_issue(smu, A, B, 0, tid);  CPCOMMIT();
  proj_issue(smu + 36864u, A, B, 32, tid);  CPCOMMIT();
  for (int t = 0; t < 32; t++) {
    if (t < 31) CPWAIT(1); else CPWAIT(0);
    __syncthreads();
    if (t + 2 < 32) {
      proj_issue(smu + (unsigned)((t+2)%3)*36864u, A, B, (t+2)*32, tid);
      CPCOMMIT();
    }
    const float* base = sm + (t%3)*9216;
    compute_tf<4,4,36,4,RNDA>(base, base + 4608, wm0, wn0, acc);
  }
#pragma unroll
  for (int mt = 0; mt < 4; mt++) {
#pragma unroll
    for (int nt = 0; nt < 4; nt++) {
      int row = m0 + wm0 + 16*mt + gr;
      int col = n0 + wn0 + 8*nt + 2*q;
      float b0 = bias[col], b1 = bias[col+1];
      float v0 = acc[mt][nt][0] + b0, v1 = acc[mt][nt][1] + b1;
      float v2 = acc[mt][nt][2] + b0, v3 = acc[mt][nt][3] + b1;
      if (epi == 0) {
        *(float2*)&Cf[(size_t)row*1024 + col]     = make_float2(rtf(v0), rtf(v1));
        *(float2*)&Cf[(size_t)(row+8)*1024 + col] = make_float2(rtf(v2), rtf(v3));
      } else if (epi == 1) {
        *(float2*)&Cf[(size_t)row*1024 + col]     = make_float2(v0, v1);
        *(float2*)&Cf[(size_t)(row+8)*1024 + col] = make_float2(v2, v3);
      } else {
        int nb = row >> 10, s = row & 1023;
        int h = col >> 6, d = col & 63;
        float* p = Cf + (((size_t)(nb*16 + h))*64 + d)*1024 + s;
        p[0] = rtf(v0); p[1024] = rtf(v1); p[8] = rtf(v2); p[1024 + 8] = rtf(v3);
      }
    }
  }
}

// Fused Q/K/V projections: z selects input/weight/bias/output/epi.
__global__ __launch_bounds__(256, 2) void proj_qkv(
    const float* __restrict__ q, const float* __restrict__ k,
    const float* __restrict__ v, const float* __restrict__ Wt4,
    const float* __restrict__ bq, const float* __restrict__ bk,
    const float* __restrict__ bv,
    float* __restrict__ Qp, float* __restrict__ Kp, float* __restrict__ Vtp) {
  extern __shared__ float sm[];
  const int z = blockIdx.z;
  const float* Af  = z == 0 ? q : z == 1 ? k : v;
  const float* Wt  = Wt4 + (size_t)z*Esz*Esz;
  const float* bias = z == 0 ? bq : z == 1 ? bk : bv;
  float* Cf = z == 0 ? Qp : z == 1 ? Kp : Vtp;
  int epi = z == 2 ? 2 : 0;
  proj_core<true>(sm, Af, Wt, bias, Cf, epi, blockIdx.y*128, blockIdx.x*128);
}

// Output projection (reads rounded g_O, writes final fp32).
__global__ __launch_bounds__(256, 2) void proj_out(
    const float* __restrict__ Af, const float* __restrict__ Wt,
    const float* __restrict__ bias, float* __restrict__ Cf) {
  extern __shared__ float sm[];
  proj_core<false>(sm, Af, Wt, bias, Cf, 1, blockIdx.y*128, blockIdx.x*128);
}

// ---------------------------------------------------------------------------
// QK^T (tf32) -> e = exp(masked/scaled logit) stored fp16 + atomic row sums.
// dyn smem 69632.
// ---------------------------------------------------------------------------
__global__ __launch_bounds__(256, 2) void qk_tf(__half* __restrict__ Pe) {
  extern __shared__ float sm[];
  const int tid = threadIdx.x, wid = tid >> 5, lane = tid & 31;
  const int gr = lane >> 2, q = lane & 3;
  const int wm0 = (wid >> 2)*64, wn0 = (wid & 3)*32;
  const int t0 = blockIdx.x*128, m0 = blockIdx.y*128;
  const int nh = blockIdx.z, nb = nh >> 4, h = nh & 15;
  unsigned smu = (unsigned)__cvta_generic_to_shared(sm);
  const float* Qb = g_Q + (size_t)(nb*1024 + m0)*1024 + h*64;
  const float* Kb = g_K + (size_t)(nb*1024 + t0)*1024 + h*64;
#pragma unroll
  for (int j = 0; j < 8; j++) {
    int c = tid + 256*j;
    int row = c >> 4, ch = c & 15;
    unsigned d = smu + (unsigned)((row*68 + ch*4)*4);
    CPA16(d,          Qb + (size_t)row*1024 + ch*4);
    CPA16(d + 34816u, Kb + (size_t)row*1024 + ch*4);
  }
  CPCOMMIT();
  CPWAIT(0);
  __syncthreads();
  float acc[4][4][4] = {};
  compute_tf<4,4,68,8>(sm, sm + 8704, wm0, wn0, acc);
  const int wcol = (t0 + wn0) >> 5;
  float rs[4][2] = {};
#pragma unroll
  for (int mt = 0; mt < 4; mt++) {
    int row = m0 + wm0 + 16*mt + gr;
    unsigned w0 = g_mbits[((size_t)nb*1024 + row)*32 + wcol];
    unsigned w1 = g_mbits[((size_t)nb*1024 + row + 8)*32 + wcol];
#pragma unroll
    for (int nt = 0; nt < 4; nt++) {
      int t = t0 + wn0 + 8*nt + 2*q;
      int b = 8*nt + 2*q;
      float2 v0, v1;
      v0.x = ((w0 >> b) & 1)     ? 0.f : __expf(acc[mt][nt][0]*0.125f);
      v0.y = ((w0 >> (b+1)) & 1) ? 0.f : __expf(acc[mt][nt][1]*0.125f);
      v1.x = ((w1 >> b) & 1)     ? 0.f : __expf(acc[mt][nt][2]*0.125f);
      v1.y = ((w1 >> (b+1)) & 1) ? 0.f : __expf(acc[mt][nt][3]*0.125f);
      rs[mt][0] += v0.x + v0.y;
      rs[mt][1] += v1.x + v1.y;
      *(__half2*)&Pe[((size_t)nh*1024 + row)*1024 + t]     = __floats2half2_rn(v0.x, v0.y);
      *(__half2*)&Pe[((size_t)nh*1024 + row + 8)*1024 + t] = __floats2half2_rn(v1.x, v1.y);
    }
  }
#pragma unroll
  for (int off = 1; off <= 2; off <<= 1) {
#pragma unroll
    for (int mt = 0; mt < 4; mt++) {
      rs[mt][0] += __shfl_xor_sync(0xffffffffu, rs[mt][0], off);
      rs[mt][1] += __shfl_xor_sync(0xffffffffu, rs[mt][1], off);
    }
  }
  if (q == 0) {
#pragma unroll
    for (int mt = 0; mt < 4; mt++) {
      int row = m0 + wm0 + 16*mt + gr;
      atomicAdd(&g_rowsum[(size_t)nh*1024 + row], rs[mt][0]);
      atomicAdd(&g_rowsum[(size_t)nh*1024 + row + 8], rs[mt][1]);
    }
  }
}

// ---------------------------------------------------------------------------
// Fused normalize + PV (tf32). Reads fp16 e, p = e*inv: streams fp32 p to the
// final attn output, stages rtf(p) for mma vs Vt. Register-prefetched A,
// 4-slot depth-2 cp.async B ring, ONE sync per iter. dyn smem 73728.
// ---------------------------------------------------------------------------
__global__ __launch_bounds__(256, 2) void pv_tf(
    const __half* __restrict__ Pe, float* __restrict__ Pout) {
  extern __shared__ float sm[];           // As: 2x4608 | Bs: 4x2304
  float* As = sm;
  float* Bs = sm + 9216;
  unsigned bsu = (unsigned)__cvta_generic_to_shared(Bs);
  const int tid = threadIdx.x, wid = tid >> 5, lane = tid & 31;
  const int gr = lane >> 2, q = lane & 3;
  const int wm0 = (wid >> 2)*64, wn0 = (wid & 3)*16;
  const int m0 = blockIdx.x*128;
  const int nh = blockIdx.y, nb = nh >> 4, h = nh & 15;
  const __half* Ps = Pe + (size_t)nh*1024*1024 + (size_t)m0*1024;
  float*        Pd = Pout + (size_t)nh*1024*1024 + (size_t)m0*1024;
  const float*  Vb = g_Vt + (size_t)nh*64*1024;
  const int ar = tid >> 3, ac = (tid & 7)*4;   // A: rows ar+32j, col ac
  float inv[4];
#pragma unroll
  for (int j = 0; j < 4; j++)
    inv[j] = 1.0f / fmaxf(g_rowsum[(size_t)nh*1024 + m0 + ar + 32*j], 1e-30f);

  auto issueB = [&](int kt, int b) {
#pragma unroll
    for (int j = 0; j < 2; j++) {
      int e = tid + 256*j;
      int m = e >> 3, kq = e & 7;
      if (m < 64) {
        unsigned d = bsu + (unsigned)(b*2304*4 + (m*36 + 4*kq)*4);
        CPA16(d, Vb + (size_t)m*1024 + kt + 4*kq);
      }
    }
  };
  issueB(0, 0);  CPCOMMIT();
  issueB(32, 1); CPCOMMIT();
  uint2 v16[4];
#pragma unroll
  for (int j = 0; j < 4; j++)
    v16[j] = *(const uint2*)(Ps + (size_t)(ar + 32*j)*1024 + ac);

  float acc[4][2][4] = {};
  for (int t = 0; t < 32; t++) {
    if (t + 2 < 32) issueB((t+2)*32, (t+2)&3);
    CPCOMMIT();
    float* Aslot = As + (t&1)*4608;
#pragma unroll
    for (int j = 0; j < 4; j++) {
      __half2 h0 = *reinterpret_cast<__half2*>(&v16[j].x);
      __half2 h1 = *reinterpret_cast<__half2*>(&v16[j].y);
      float2 f0 = __half22float2(h0), f1 = __half22float2(h1);
      float iv = inv[j];
      float4 p;
      p.x = f0.x*iv; p.y = f0.y*iv; p.z = f1.x*iv; p.w = f1.y*iv;
      *(float4*)(Pd + (size_t)(ar + 32*j)*1024 + t*32 + ac) = p;
      p.x = rtf(p.x); p.y = rtf(p.y); p.z = rtf(p.z); p.w = rtf(p.w);
      *(float4*)&Aslot[(ar + 32*j)*36 + ac] = p;
    }
    if (t + 1 < 32) {
#pragma unroll
      for (int j = 0; j < 4; j++)
        v16[j] = *(const uint2*)(Ps + (size_t)(ar + 32*j)*1024 + (t+1)*32 + ac);
    }
    CPWAIT(2);
    __syncthreads();
    compute_tf<4,2,36,4>(Aslot, Bs + (t&3)*2304, wm0, wn0, acc);
  }
#pragma unroll
  for (int mt = 0; mt < 4; mt++) {
#pragma unroll
    for (int nt = 0; nt < 2; nt++) {
      int s = m0 + wm0 + 16*mt + gr;
      int col = h*64 + wn0 + 8*nt + 2*q;
      *(float2*)&g_O[(size_t)(nb*1024 + s)*1024 + col] =
          make_float2(rtf(acc[mt][nt][0]), rtf(acc[mt][nt][1]));
      *(float2*)&g_O[(size_t)(nb*1024 + s + 8)*1024 + col] =
          make_float2(rtf(acc[mt][nt][2]), rtf(acc[mt][nt][3]));
    }
  }
}

// ---------------------------------------------------------------------------
extern "C" void kernel_launch(void* const* d_in, const int* in_sizes, int n_in,
                              void* d_out, int out_size) {
  const float* q  = (const float*)d_in[0];
  const float* k  = (const float*)d_in[1];
  const float* v  = (const float*)d_in[2];
  const int*   mask = (const int*)d_in[3];
  const float* wq = (const float*)d_in[4];
  const float* bq = (const float*)d_in[5];
  const float* wk = (const float*)d_in[6];
  const float* bk = (const float*)d_in[7];
  const float* wv = (const float*)d_in[8];
  const float* bv = (const float*)d_in[9];
  const float* wo = (const float*)d_in[10];
  const float* bo = (const float*)d_in[11];
  float* out = (float*)d_out;

  static bool attr_done = false;
  if (!attr_done) {
    cudaFuncSetAttribute(proj_qkv, cudaFuncAttributeMaxDynamicSharedMemorySize, 110592);
    cudaFuncSetAttribute(proj_out, cudaFuncAttributeMaxDynamicSharedMemorySize, 110592);
    cudaFuncSetAttribute(qk_tf, cudaFuncAttributeMaxDynamicSharedMemorySize, 69632);
    cudaFuncSetAttribute(pv_tf, cudaFuncAttributeMaxDynamicSharedMemorySize, 73728);
    attr_done = true;
  }

  float *Qp, *Kp, *Vtp, *Op, *Wtp, *attn, *rowsum;
  __half* Pe;
  unsigned* mb;
  cudaGetSymbolAddress((void**)&Qp, g_Q);
  cudaGetSymbolAddress((void**)&Kp, g_K);
  cudaGetSymbolAddress((void**)&Vtp, g_Vt);
  cudaGetSymbolAddress((void**)&Op, g_O);
  cudaGetSymbolAddress((void**)&Wtp, g_Wt);
  cudaGetSymbolAddress((void**)&mb, g_mbits);
  cudaGetSymbolAddress((void**)&rowsum, g_rowsum);
  cudaGetSymbolAddress((void**)&Pe, g_Pe);
  if ((long long)out_size >= (long long)NSE + (long long)NHSS) {
    attn = out + NSE;
  } else {
    cudaGetSymbolAddress((void**)&attn, g_attn_fb);
  }

  cudaMemsetAsync(rowsum, 0, NROWS*sizeof(float));

  transpose_round4<<<dim3(32, 32, 4), 256>>>(wq, wk, wv, wo, Wtp);
  mask_bits<<<1024, 256>>>(mask, mb);

  proj_qkv<<<dim3(8, 64, 3), 256, 110592>>>(q, k, v, Wtp, bq, bk, bv, Qp, Kp, Vtp);
  qk_tf<<<dim3(8, 8, 128), 256, 69632>>>(Pe);
  pv_tf<<<dim3(8, 128), 256, 73728>>>(Pe, attn);
  proj_out<<<dim3(8, 64), 256, 110592>>>(Op, Wtp + 3*Esz*Esz, bo, out);
}

// round 17
// speedup vs baseline: 1.4756x; 1.4756x over previous
#include <cuda_runtime.h>
#include <cuda_fp16.h>
#include <cstdint>

#define Nb  8
#define Ssz 1024
#define Esz 1024
#define Hn  16
#define DKs 64
#define NSE (Nb*Ssz*Esz)                 // 8388608
#define NHSS (134217728)
#define NMW (Nb*Ssz*32)                  // mask words: 262144
#define NROWS (Hn*Nb*Ssz)                // 131072

// fp32 buffers (tf32-rounded values stored as fp32)
__device__ float g_Q[NSE], g_K[NSE];     // rounded Q,K [n,s,h,d]
__device__ float g_Vt[NSE];              // rounded V transposed [nh][d][t]
__device__ float g_O[NSE];               // rounded attention output
__device__ float g_Wt[4*Esz*Esz];        // rounded transposed weights [n][k]
__device__ unsigned g_mbits[NMW];        // mask bitwords [nb][row][col/32]
__device__ float g_rowsum[NROWS];        // per (nh,row) sum of exp
__device__ __half g_Pe[NHSS];            // exp scratch (softmax numerators, fp16)
__device__ float g_attn_fb[NHSS];        // fallback attn output (never in practice)

#define CPA16(saddr, gptr) asm volatile("cp.async.cg.shared.global [%0], [%1], 16;\n" :: "r"(saddr), "l"(gptr))
#define CPCOMMIT() asm volatile("cp.async.commit_group;\n")
#define CPWAIT(n)  asm volatile("cp.async.wait_group %0;\n" :: "n"(n))
#define LDSM4(r0,r1,r2,r3,a) asm volatile( \
  "ldmatrix.sync.aligned.m8n8.x4.shared.b16 {%0,%1,%2,%3}, [%4];" \
  : "=r"(r0),"=r"(r1),"=r"(r2),"=r"(r3) : "r"(a))
#define LDSM2(r0,r1,a) asm volatile( \
  "ldmatrix.sync.aligned.m8n8.x2.shared.b16 {%0,%1}, [%2];" \
  : "=r"(r0),"=r"(r1) : "r"(a))

__device__ __forceinline__ float rtf(float x) {
  unsigned u;
  asm("cvt.rna.tf32.f32 %0, %1;" : "=r"(u) : "f"(x));
  return __uint_as_float(u);
}
__device__ __forceinline__ unsigned rtfu(unsigned x) {
  unsigned u;
  asm("cvt.rna.tf32.f32 %0, %1;" : "=r"(u) : "r"(x));
  return u;
}

__device__ __forceinline__ void mma8(float* c, const unsigned* a, unsigned b0, unsigned b1) {
  asm volatile(
      "mma.sync.aligned.m16n8k8.row.col.f32.tf32.tf32.f32 "
      "{%0,%1,%2,%3}, {%4,%5,%6,%7}, {%8,%9}, {%0,%1,%2,%3};\n"
      : "+f"(c[0]), "+f"(c[1]), "+f"(c[2]), "+f"(c[3])
      : "r"(a[0]), "r"(a[1]), "r"(a[2]), "r"(a[3]), "r"(b0), "r"(b1));
}

// tf32 warp-tile compute over CH k8-chunks. A,B fp32 smem tiles, pitch in words.
// RNDA: apply tf32 rounding to A fragments in registers (for raw fp32 A).
template <int MT, int NT, int PITCH, int CH, bool RNDA = false>
__device__ __forceinline__ void compute_tf(
    const float* A, const float* B, int wm0, int wn0, float (&acc)[MT][NT][4]) {
  const int lane = threadIdx.x & 31;
  unsigned aA = (unsigned)__cvta_generic_to_shared(A);
  unsigned aB = (unsigned)__cvta_generic_to_shared(B);
#pragma unroll
  for (int c = 0; c < CH; c++) {
    unsigned a[MT][4];
#pragma unroll
    for (int mt = 0; mt < MT; mt++) {
      unsigned off = (unsigned)((((wm0 + 16*mt + (lane & 15))*PITCH) + c*8 + (lane >> 4)*4)*4);
      LDSM4(a[mt][0], a[mt][1], a[mt][2], a[mt][3], aA + off);
      if (RNDA) {
        a[mt][0] = rtfu(a[mt][0]); a[mt][1] = rtfu(a[mt][1]);
        a[mt][2] = rtfu(a[mt][2]); a[mt][3] = rtfu(a[mt][3]);
      }
    }
#pragma unroll
    for (int nt = 0; nt < NT; nt++) {
      unsigned off = (unsigned)((((wn0 + 8*nt + (lane & 7))*PITCH) + c*8 + ((lane >> 3) & 1)*4)*4);
      unsigned b0, b1;
      LDSM2(b0, b1, aB + off);
#pragma unroll
      for (int mt = 0; mt < MT; mt++) mma8(acc[mt][nt], a[mt], b0, b1);
    }
  }
}

// All 4 weight transposes in one launch: W[k][n] -> Wt[n][k], rounded. z=which.
__global__ __launch_bounds__(256) void transpose_round4(
    const float* __restrict__ w0, const float* __restrict__ w1,
    const float* __restrict__ w2, const float* __restrict__ w3,
    float* __restrict__ WtBase) {
  const float* W = blockIdx.z == 0 ? w0 : blockIdx.z == 1 ? w1 :
                   blockIdx.z == 2 ? w2 : w3;
  float* Wt = WtBase + (size_t)blockIdx.z*Esz*Esz;
  __shared__ float tile[32][33];
  int bx = blockIdx.x*32, by = blockIdx.y*32;
  int t = threadIdx.x, x = t & 31, y = t >> 5;
#pragma unroll
  for (int i = 0; i < 4; i++)
    tile[y + 8*i][x] = W[(size_t)(by + y + 8*i)*1024 + bx + x];
  __syncthreads();
#pragma unroll
  for (int i = 0; i < 4; i++)
    Wt[(size_t)(bx + y + 8*i)*1024 + by + x] = rtf(tile[x][y + 8*i]);
}

// mask int32 -> 1 bit per entry
__global__ void mask_bits(const int* __restrict__ mask, unsigned* __restrict__ mb) {
  int lane = threadIdx.x & 31;
  int warp = (blockIdx.x*blockDim.x + threadIdx.x) >> 5;
  int nwarps = (gridDim.x*blockDim.x) >> 5;
  for (int w = warp; w < NMW; w += nwarps) {
    int v = mask[(size_t)w*32 + lane];
    unsigned b = __ballot_sync(0xffffffffu, v != 0);
    if (lane == 0) mb[w] = b;
  }
}

// load 128x32 fp32 tile into stage (pitch 36 words)
__device__ __forceinline__ void proj_issue(
    unsigned st, const float* __restrict__ A, const float* __restrict__ B,
    int kt, int tid) {
#pragma unroll
  for (int j = 0; j < 4; j++) {
    int c = tid + 256*j;
    int row = c >> 3, ch = c & 7;
    unsigned d = st + (unsigned)((row*36 + ch*4)*4);
    CPA16(d,          A + (size_t)row*1024 + kt + ch*4);
    CPA16(d + 18432u, B + (size_t)row*1024 + kt + ch*4);
  }
}

// ---------------------------------------------------------------------------
// Projection GEMM core (tf32) — R15-proven mainloop: 2-stage cp.async,
// CPWAIT+sync before compute, sync after. dyn smem 73728.
// epi: 0 = rounded fp32 (Q/K), 1 = plain fp32 out, 2 = rounded Vt-transposed.
// ---------------------------------------------------------------------------
template <bool RNDA>
__device__ __forceinline__ void proj_core(
    float* sm, const float* Af, const float* Wt, const float* bias,
    float* Cf, int epi, int m0, int n0) {
  const int tid = threadIdx.x, wid = tid >> 5, lane = tid & 31;
  const int gr = lane >> 2, q = lane & 3;
  const int wm0 = (wid >> 2)*64, wn0 = (wid & 3)*32;
  unsigned smu = (unsigned)__cvta_generic_to_shared(sm);
  const float* A = Af + (size_t)m0*1024;
  const float* B = Wt + (size_t)n0*1024;
  float acc[4][4][4] = {};
  proj_issue(smu, A, B, 0, tid);
  CPCOMMIT();
  for (int t = 0; t < 32; t++) {
    if (t + 1 < 32)
      proj_issue(smu + ((t+1)&1)*36864u, A, B, (t+1)*32, tid);
    CPCOMMIT();
    CPWAIT(1);
    __syncthreads();
    const float* base = sm + (t&1)*9216;
    compute_tf<4,4,36,4,RNDA>(base, base + 4608, wm0, wn0, acc);
    __syncthreads();
  }
#pragma unroll
  for (int mt = 0; mt < 4; mt++) {
#pragma unroll
    for (int nt = 0; nt < 4; nt++) {
      int row = m0 + wm0 + 16*mt + gr;
      int col = n0 + wn0 + 8*nt + 2*q;
      float b0 = bias[col], b1 = bias[col+1];
      float v0 = acc[mt][nt][0] + b0, v1 = acc[mt][nt][1] + b1;
      float v2 = acc[mt][nt][2] + b0, v3 = acc[mt][nt][3] + b1;
      if (epi == 0) {
        *(float2*)&Cf[(size_t)row*1024 + col]     = make_float2(rtf(v0), rtf(v1));
        *(float2*)&Cf[(size_t)(row+8)*1024 + col] = make_float2(rtf(v2), rtf(v3));
      } else if (epi == 1) {
        *(float2*)&Cf[(size_t)row*1024 + col]     = make_float2(v0, v1);
        *(float2*)&Cf[(size_t)(row+8)*1024 + col] = make_float2(v2, v3);
      } else {
        int nb = row >> 10, s = row & 1023;
        int h = col >> 6, d = col & 63;
        float* p = Cf + (((size_t)(nb*16 + h))*64 + d)*1024 + s;
        p[0] = rtf(v0); p[1024] = rtf(v1); p[8] = rtf(v2); p[1024 + 8] = rtf(v3);
      }
    }
  }
}

// Fused Q/K/V projections: z selects input/weight/bias/output/epi.
__global__ __launch_bounds__(256, 2) void proj_qkv(
    const float* __restrict__ q, const float* __restrict__ k,
    const float* __restrict__ v, const float* __restrict__ Wt4,
    const float* __restrict__ bq, const float* __restrict__ bk,
    const float* __restrict__ bv,
    float* __restrict__ Qp, float* __restrict__ Kp, float* __restrict__ Vtp) {
  extern __shared__ float sm[];
  const int z = blockIdx.z;
  const float* Af  = z == 0 ? q : z == 1 ? k : v;
  const float* Wt  = Wt4 + (size_t)z*Esz*Esz;
  const float* bias = z == 0 ? bq : z == 1 ? bk : bv;
  float* Cf = z == 0 ? Qp : z == 1 ? Kp : Vtp;
  int epi = z == 2 ? 2 : 0;
  proj_core<true>(sm, Af, Wt, bias, Cf, epi, blockIdx.y*128, blockIdx.x*128);
}

// Output projection (reads rounded g_O, writes final fp32).
__global__ __launch_bounds__(256, 2) void proj_out(
    const float* __restrict__ Af, const float* __restrict__ Wt,
    const float* __restrict__ bias, float* __restrict__ Cf) {
  extern __shared__ float sm[];
  proj_core<false>(sm, Af, Wt, bias, Cf, 1, blockIdx.y*128, blockIdx.x*128);
}

// ---------------------------------------------------------------------------
// QK^T (tf32) -> e = exp(masked/scaled logit) stored fp16 + atomic row sums.
// dyn smem 69632.
// ---------------------------------------------------------------------------
__global__ __launch_bounds__(256, 2) void qk_tf(__half* __restrict__ Pe) {
  extern __shared__ float sm[];
  const int tid = threadIdx.x, wid = tid >> 5, lane = tid & 31;
  const int gr = lane >> 2, q = lane & 3;
  const int wm0 = (wid >> 2)*64, wn0 = (wid & 3)*32;
  const int t0 = blockIdx.x*128, m0 = blockIdx.y*128;
  const int nh = blockIdx.z, nb = nh >> 4, h = nh & 15;
  unsigned smu = (unsigned)__cvta_generic_to_shared(sm);
  const float* Qb = g_Q + (size_t)(nb*1024 + m0)*1024 + h*64;
  const float* Kb = g_K + (size_t)(nb*1024 + t0)*1024 + h*64;
#pragma unroll
  for (int j = 0; j < 8; j++) {
    int c = tid + 256*j;
    int row = c >> 4, ch = c & 15;
    unsigned d = smu + (unsigned)((row*68 + ch*4)*4);
    CPA16(d,          Qb + (size_t)row*1024 + ch*4);
    CPA16(d + 34816u, Kb + (size_t)row*1024 + ch*4);
  }
  CPCOMMIT();
  CPWAIT(0);
  __syncthreads();
  float acc[4][4][4] = {};
  compute_tf<4,4,68,8>(sm, sm + 8704, wm0, wn0, acc);
  const int wcol = (t0 + wn0) >> 5;
  float rs[4][2] = {};
#pragma unroll
  for (int mt = 0; mt < 4; mt++) {
    int row = m0 + wm0 + 16*mt + gr;
    unsigned w0 = g_mbits[((size_t)nb*1024 + row)*32 + wcol];
    unsigned w1 = g_mbits[((size_t)nb*1024 + row + 8)*32 + wcol];
#pragma unroll
    for (int nt = 0; nt < 4; nt++) {
      int t = t0 + wn0 + 8*nt + 2*q;
      int b = 8*nt + 2*q;
      float2 v0, v1;
      v0.x = ((w0 >> b) & 1)     ? 0.f : __expf(acc[mt][nt][0]*0.125f);
      v0.y = ((w0 >> (b+1)) & 1) ? 0.f : __expf(acc[mt][nt][1]*0.125f);
      v1.x = ((w1 >> b) & 1)     ? 0.f : __expf(acc[mt][nt][2]*0.125f);
      v1.y = ((w1 >> (b+1)) & 1) ? 0.f : __expf(acc[mt][nt][3]*0.125f);
      rs[mt][0] += v0.x + v0.y;
      rs[mt][1] += v1.x + v1.y;
      *(__half2*)&Pe[((size_t)nh*1024 + row)*1024 + t]     = __floats2half2_rn(v0.x, v0.y);
      *(__half2*)&Pe[((size_t)nh*1024 + row + 8)*1024 + t] = __floats2half2_rn(v1.x, v1.y);
    }
  }
#pragma unroll
  for (int off = 1; off <= 2; off <<= 1) {
#pragma unroll
    for (int mt = 0; mt < 4; mt++) {
      rs[mt][0] += __shfl_xor_sync(0xffffffffu, rs[mt][0], off);
      rs[mt][1] += __shfl_xor_sync(0xffffffffu, rs[mt][1], off);
    }
  }
  if (q == 0) {
#pragma unroll
    for (int mt = 0; mt < 4; mt++) {
      int row = m0 + wm0 + 16*mt + gr;
      atomicAdd(&g_rowsum[(size_t)nh*1024 + row], rs[mt][0]);
      atomicAdd(&g_rowsum[(size_t)nh*1024 + row + 8], rs[mt][1]);
    }
  }
}

// ---------------------------------------------------------------------------
// Fused normalize + PV (tf32). Reads fp16 e, p = e*inv: streams fp32 p to the
// final attn output, stages rtf(p) for mma vs Vt. Register-prefetched A,
// 4-slot depth-2 cp.async B ring, ONE sync per iter. dyn smem 73728.
// ---------------------------------------------------------------------------
__global__ __launch_bounds__(256, 2) void pv_tf(
    const __half* __restrict__ Pe, float* __restrict__ Pout) {
  extern __shared__ float sm[];           // As: 2x4608 | Bs: 4x2304
  float* As = sm;
  float* Bs = sm + 9216;
  unsigned bsu = (unsigned)__cvta_generic_to_shared(Bs);
  const int tid = threadIdx.x, wid = tid >> 5, lane = tid & 31;
  const int gr = lane >> 2, q = lane & 3;
  const int wm0 = (wid >> 2)*64, wn0 = (wid & 3)*16;
  const int m0 = blockIdx.x*128;
  const int nh = blockIdx.y, nb = nh >> 4, h = nh & 15;
  const __half* Ps = Pe + (size_t)nh*1024*1024 + (size_t)m0*1024;
  float*        Pd = Pout + (size_t)nh*1024*1024 + (size_t)m0*1024;
  const float*  Vb = g_Vt + (size_t)nh*64*1024;
  const int ar = tid >> 3, ac = (tid & 7)*4;   // A: rows ar+32j, col ac
  float inv[4];
#pragma unroll
  for (int j = 0; j < 4; j++)
    inv[j] = 1.0f / fmaxf(g_rowsum[(size_t)nh*1024 + m0 + ar + 32*j], 1e-30f);

  auto issueB = [&](int kt, int b) {
#pragma unroll
    for (int j = 0; j < 2; j++) {
      int e = tid + 256*j;
      int m = e >> 3, kq = e & 7;
      if (m < 64) {
        unsigned d = bsu + (unsigned)(b*2304*4 + (m*36 + 4*kq)*4);
        CPA16(d, Vb + (size_t)m*1024 + kt + 4*kq);
      }
    }
  };
  issueB(0, 0);  CPCOMMIT();
  issueB(32, 1); CPCOMMIT();
  uint2 v16[4];
#pragma unroll
  for (int j = 0; j < 4; j++)
    v16[j] = *(const uint2*)(Ps + (size_t)(ar + 32*j)*1024 + ac);

  float acc[4][2][4] = {};
  for (int t = 0; t < 32; t++) {
    if (t + 2 < 32) issueB((t+2)*32, (t+2)&3);
    CPCOMMIT();
    float* Aslot = As + (t&1)*4608;
#pragma unroll
    for (int j = 0; j < 4; j++) {
      __half2 h0 = *reinterpret_cast<__half2*>(&v16[j].x);
      __half2 h1 = *reinterpret_cast<__half2*>(&v16[j].y);
      float2 f0 = __half22float2(h0), f1 = __half22float2(h1);
      float iv = inv[j];
      float4 p;
      p.x = f0.x*iv; p.y = f0.y*iv; p.z = f1.x*iv; p.w = f1.y*iv;
      *(float4*)(Pd + (size_t)(ar + 32*j)*1024 + t*32 + ac) = p;
      p.x = rtf(p.x); p.y = rtf(p.y); p.z = rtf(p.z); p.w = rtf(p.w);
      *(float4*)&Aslot[(ar + 32*j)*36 + ac] = p;
    }
    if (t + 1 < 32) {
#pragma unroll
      for (int j = 0; j < 4; j++)
        v16[j] = *(const uint2*)(Ps + (size_t)(ar + 32*j)*1024 + (t+1)*32 + ac);
    }
    CPWAIT(2);
    __syncthreads();
    compute_tf<4,2,36,4>(Aslot, Bs + (t&3)*2304, wm0, wn0, acc);
  }
#pragma unroll
  for (int mt = 0; mt < 4; mt++) {
#pragma unroll
    for (int nt = 0; nt < 2; nt++) {
      int s = m0 + wm0 + 16*mt + gr;
      int col = h*64 + wn0 + 8*nt + 2*q;
      *(float2*)&g_O[(size_t)(nb*1024 + s)*1024 + col] =
          make_float2(rtf(acc[mt][nt][0]), rtf(acc[mt][nt][1]));
      *(float2*)&g_O[(size_t)(nb*1024 + s + 8)*1024 + col] =
          make_float2(rtf(acc[mt][nt][2]), rtf(acc[mt][nt][3]));
    }
  }
}

// ---------------------------------------------------------------------------
extern "C" void kernel_launch(void* const* d_in, const int* in_sizes, int n_in,
                              void* d_out, int out_size) {
  const float* q  = (const float*)d_in[0];
  const float* k  = (const float*)d_in[1];
  const float* v  = (const float*)d_in[2];
  const int*   mask = (const int*)d_in[3];
  const float* wq = (const float*)d_in[4];
  const float* bq = (const float*)d_in[5];
  const float* wk = (const float*)d_in[6];
  const float* bk = (const float*)d_in[7];
  const float* wv = (const float*)d_in[8];
  const float* bv = (const float*)d_in[9];
  const float* wo = (const float*)d_in[10];
  const float* bo = (const float*)d_in[11];
  float* out = (float*)d_out;

  static bool attr_done = false;
  if (!attr_done) {
    cudaFuncSetAttribute(proj_qkv, cudaFuncAttributeMaxDynamicSharedMemorySize, 73728);
    cudaFuncSetAttribute(proj_out, cudaFuncAttributeMaxDynamicSharedMemorySize, 73728);
    cudaFuncSetAttribute(qk_tf, cudaFuncAttributeMaxDynamicSharedMemorySize, 69632);
    cudaFuncSetAttribute(pv_tf, cudaFuncAttributeMaxDynamicSharedMemorySize, 73728);
    attr_done = true;
  }

  float *Qp, *Kp, *Vtp, *Op, *Wtp, *attn, *rowsum;
  __half* Pe;
  unsigned* mb;
  cudaGetSymbolAddress((void**)&Qp, g_Q);
  cudaGetSymbolAddress((void**)&Kp, g_K);
  cudaGetSymbolAddress((void**)&Vtp, g_Vt);
  cudaGetSymbolAddress((void**)&Op, g_O);
  cudaGetSymbolAddress((void**)&Wtp, g_Wt);
  cudaGetSymbolAddress((void**)&mb, g_mbits);
  cudaGetSymbolAddress((void**)&rowsum, g_rowsum);
  cudaGetSymbolAddress((void**)&Pe, g_Pe);
  if ((long long)out_size >= (long long)NSE + (long long)NHSS) {
    attn = out + NSE;
  } else {
    cudaGetSymbolAddress((void**)&attn, g_attn_fb);
  }

  cudaMemsetAsync(rowsum, 0, NROWS*sizeof(float));

  transpose_round4<<<dim3(32, 32, 4), 256>>>(wq, wk, wv, wo, Wtp);
  mask_bits<<<1024, 256>>>(mask, mb);

  proj_qkv<<<dim3(8, 64, 3), 256, 73728>>>(q, k, v, Wtp, bq, bk, bv, Qp, Kp, Vtp);
  qk_tf<<<dim3(8, 8, 128), 256, 69632>>>(Pe);
  pv_tf<<<dim3(8, 128), 256, 73728>>>(Pe, attn);
  proj_out<<<dim3(8, 64), 256, 73728>>>(Op, Wtp + 3*Esz*Esz, bo, out);
}